// round 1
// baseline (speedup 1.0000x reference)
#include <cuda_runtime.h>

#define NMAX_NODES 50048
#define FEAT 128

// Device scratch (no allocations allowed in kernel_launch).
__device__ float g_rep[NMAX_NODES * FEAT];   // pre-relu nodes_rep = F @ W
__device__ float g_sum[NMAX_NODES * FEAT];   // segment sum of rep[src] per dst
__device__ float g_cnt[NMAX_NODES];          // in-degree counts

// ---------------------------------------------------------------------------
// K1: zero the accumulation scratch
// ---------------------------------------------------------------------------
__global__ void zero_kernel(int n_nodes) {
    int tid = blockIdx.x * blockDim.x + threadIdx.x;
    int stride = gridDim.x * blockDim.x;
    int total4 = n_nodes * (FEAT / 4);
    for (int i = tid; i < total4; i += stride)
        ((float4*)g_sum)[i] = make_float4(0.f, 0.f, 0.f, 0.f);
    for (int j = tid; j < n_nodes; j += stride)
        g_cnt[j] = 0.f;
}

// ---------------------------------------------------------------------------
// K2: rep = F @ W  (fp32),  out[:, 0:128] = relu(rep)
// Block: 256 threads, tile 64 rows x 128 cols, thread microtile 8x4.
// Smem: W half-K (64x128 = 32KB) + F tile (64x64 = 16KB) = 48KB static.
// ---------------------------------------------------------------------------
__global__ __launch_bounds__(256) void gemm_kernel(
    const float* __restrict__ feat, const float* __restrict__ W,
    float* __restrict__ out, int n_nodes)
{
    __shared__ float Ws[64 * 128];
    __shared__ float Fs[64 * 64];

    const int tx = threadIdx.x & 31;   // 32 col-groups (4 cols each)
    const int ty = threadIdx.x >> 5;   // 8 row-groups (8 rows each)
    const int row0 = blockIdx.x * 64;

    float acc[8][4];
    #pragma unroll
    for (int r = 0; r < 8; r++)
        #pragma unroll
        for (int c = 0; c < 4; c++) acc[r][c] = 0.f;

    for (int kk = 0; kk < 128; kk += 64) {
        // stage W rows [kk, kk+64) : 2048 float4
        for (int t = threadIdx.x; t < 64 * 128 / 4; t += 256)
            ((float4*)Ws)[t] = ((const float4*)(W + kk * 128))[t];
        // stage F tile rows [row0, row0+64), cols [kk, kk+64) : 1024 float4
        for (int t = threadIdx.x; t < 64 * 64 / 4; t += 256) {
            int r  = t >> 4;       // 16 float4 per row
            int c4 = t & 15;
            int grow = row0 + r;
            float4 v = make_float4(0.f, 0.f, 0.f, 0.f);
            if (grow < n_nodes)
                v = *(const float4*)(feat + (size_t)grow * 128 + kk + c4 * 4);
            ((float4*)Fs)[t] = v;
        }
        __syncthreads();

        #pragma unroll 16
        for (int k = 0; k < 64; k++) {
            float4 w = *(const float4*)(Ws + k * 128 + tx * 4);
            #pragma unroll
            for (int r = 0; r < 8; r++) {
                float f = Fs[(ty * 8 + r) * 64 + k];   // warp-broadcast LDS
                acc[r][0] += f * w.x;
                acc[r][1] += f * w.y;
                acc[r][2] += f * w.z;
                acc[r][3] += f * w.w;
            }
        }
        __syncthreads();
    }

    #pragma unroll
    for (int r = 0; r < 8; r++) {
        int row = row0 + ty * 8 + r;
        if (row >= n_nodes) continue;
        int col = tx * 4;
        float4 v = make_float4(acc[r][0], acc[r][1], acc[r][2], acc[r][3]);
        *(float4*)(g_rep + (size_t)row * 128 + col) = v;
        float4 rv = make_float4(fmaxf(v.x, 0.f), fmaxf(v.y, 0.f),
                                fmaxf(v.z, 0.f), fmaxf(v.w, 0.f));
        *(float4*)(out + (size_t)row * 256 + col) = rv;
    }
}

// ---------------------------------------------------------------------------
// K3: scatter — one warp per edge.
// sum[dst] += rep[src] (float4 atomics, sm_90+), cnt[dst] += 1
// ---------------------------------------------------------------------------
__global__ void scatter_kernel(const int* __restrict__ src,
                               const int* __restrict__ dst, int n_edges)
{
    int gwarp  = (blockIdx.x * blockDim.x + threadIdx.x) >> 5;
    int lane   = threadIdx.x & 31;
    int nwarps = (gridDim.x * blockDim.x) >> 5;
    for (int e = gwarp; e < n_edges; e += nwarps) {
        int s = src[e];
        int d = dst[e];
        float4 v = *(const float4*)(g_rep + (size_t)s * 128 + lane * 4);
        atomicAdd((float4*)(g_sum + (size_t)d * 128 + lane * 4), v);
        if (lane == 0) atomicAdd(&g_cnt[d], 1.0f);
    }
}

// ---------------------------------------------------------------------------
// K4: out[:, 128:256] = relu(sum / max(cnt, 1))
// ---------------------------------------------------------------------------
__global__ void finalize_kernel(float* __restrict__ out, int n_nodes) {
    int i = blockIdx.x * blockDim.x + threadIdx.x;   // one per (node, col4)
    int total = n_nodes * 32;
    if (i >= total) return;
    int n  = i >> 5;
    int c4 = i & 31;
    float inv = 1.0f / fmaxf(g_cnt[n], 1.0f);
    float4 v = *(const float4*)(g_sum + (size_t)n * 128 + c4 * 4);
    float4 r = make_float4(fmaxf(v.x * inv, 0.f), fmaxf(v.y * inv, 0.f),
                           fmaxf(v.z * inv, 0.f), fmaxf(v.w * inv, 0.f));
    *(float4*)(out + (size_t)n * 256 + 128 + c4 * 4) = r;
}

// ---------------------------------------------------------------------------
extern "C" void kernel_launch(void* const* d_in, const int* in_sizes, int n_in,
                              void* d_out, int out_size) {
    const float* feat = (const float*)d_in[0];
    const float* W    = (const float*)d_in[1];
    const int*   esrc = (const int*)d_in[2];
    const int*   edst = (const int*)d_in[3];
    float* out = (float*)d_out;

    int n_nodes = in_sizes[0] / FEAT;
    int n_edges = in_sizes[2];

    {   // K1: zero scratch
        int threads = 256;
        int blocks  = (n_nodes * 32 + threads - 1) / threads;
        zero_kernel<<<blocks, threads>>>(n_nodes);
    }
    {   // K2: GEMM + relu of self-representation
        int blocks = (n_nodes + 63) / 64;
        gemm_kernel<<<blocks, 256>>>(feat, W, out, n_nodes);
    }
    {   // K3: edge scatter (8 warps / block, 1 warp / edge)
        int blocks = (n_edges + 7) / 8;
        scatter_kernel<<<blocks, 256>>>(esrc, edst, n_edges);
    }
    {   // K4: mean + relu of aggregated representation
        int threads = 256;
        int blocks  = (n_nodes * 32 + threads - 1) / threads;
        finalize_kernel<<<blocks, 256>>>(out, n_nodes);
    }
}

// round 2
// speedup vs baseline: 1.2414x; 1.2414x over previous
#include <cuda_runtime.h>

#define NMAX_NODES 50048
#define EMAX 1700000
#define FEAT 128

// Device scratch (no dynamic allocation allowed).
__device__ float g_rep[NMAX_NODES * FEAT];  // nodes_rep = F @ W (pre-relu)
__device__ int   g_cnt[NMAX_NODES];         // in-degree counts
__device__ int   g_off[NMAX_NODES + 1];     // CSR row offsets
__device__ int   g_cur[NMAX_NODES];         // placement cursors
__device__ int   g_csr_src[EMAX];           // src ids grouped by dst

// ---------------------------------------------------------------------------
// K0: zero counts
// ---------------------------------------------------------------------------
__global__ void zero_cnt_kernel(int n_nodes) {
    int i = blockIdx.x * blockDim.x + threadIdx.x;
    if (i < n_nodes) g_cnt[i] = 0;
}

// ---------------------------------------------------------------------------
// K1: histogram of edge destinations
// ---------------------------------------------------------------------------
__global__ void hist_kernel(const int* __restrict__ dst, int n_edges) {
    int i = blockIdx.x * blockDim.x + threadIdx.x;
    if (i < n_edges) atomicAdd(&g_cnt[dst[i]], 1);
}

// ---------------------------------------------------------------------------
// K2: single-block exclusive scan of counts -> offsets (+ cursor copy)
// ---------------------------------------------------------------------------
__global__ __launch_bounds__(1024) void scan_kernel(int n_nodes) {
    __shared__ int warp_sums[32];
    const int tid  = threadIdx.x;
    const int lane = tid & 31, wid = tid >> 5;
    const int chunk = (n_nodes + 1023) / 1024;
    const int beg = tid * chunk;
    const int fin = min(beg + chunk, n_nodes);

    int sum = 0;
    for (int i = beg; i < fin; i++) sum += g_cnt[i];

    // warp inclusive scan
    int v = sum;
    #pragma unroll
    for (int o = 1; o < 32; o <<= 1) {
        int t = __shfl_up_sync(0xffffffffu, v, o);
        if (lane >= o) v += t;
    }
    if (lane == 31) warp_sums[wid] = v;
    __syncthreads();
    if (wid == 0) {
        int w = warp_sums[lane];
        #pragma unroll
        for (int o = 1; o < 32; o <<= 1) {
            int t = __shfl_up_sync(0xffffffffu, w, o);
            if (lane >= o) w += t;
        }
        warp_sums[lane] = w;
    }
    __syncthreads();

    int excl = (v - sum) + (wid > 0 ? warp_sums[wid - 1] : 0);
    int run = excl;
    for (int i = beg; i < fin; i++) {
        g_off[i] = run;
        g_cur[i] = run;
        run += g_cnt[i];
    }
    if (tid == 1023) g_off[n_nodes] = run;
}

// ---------------------------------------------------------------------------
// K3: place edges into CSR order (order within a segment is arbitrary)
// ---------------------------------------------------------------------------
__global__ void place_kernel(const int* __restrict__ src,
                             const int* __restrict__ dst, int n_edges) {
    int i = blockIdx.x * blockDim.x + threadIdx.x;
    if (i >= n_edges) return;
    int pos = atomicAdd(&g_cur[dst[i]], 1);
    g_csr_src[pos] = src[i];
}

// ---------------------------------------------------------------------------
// K4: rep = F @ W (fp32), out[:, 0:128] = relu(rep)
// 256 threads, 64x128 tile, 8x4 microtile, 48KB smem.
// ---------------------------------------------------------------------------
__global__ __launch_bounds__(256) void gemm_kernel(
    const float* __restrict__ feat, const float* __restrict__ W,
    float* __restrict__ out, int n_nodes)
{
    __shared__ float Ws[64 * 128];
    __shared__ float Fs[64 * 64];

    const int tx = threadIdx.x & 31;
    const int ty = threadIdx.x >> 5;
    const int row0 = blockIdx.x * 64;

    float acc[8][4];
    #pragma unroll
    for (int r = 0; r < 8; r++)
        #pragma unroll
        for (int c = 0; c < 4; c++) acc[r][c] = 0.f;

    for (int kk = 0; kk < 128; kk += 64) {
        for (int t = threadIdx.x; t < 64 * 128 / 4; t += 256)
            ((float4*)Ws)[t] = ((const float4*)(W + kk * 128))[t];
        for (int t = threadIdx.x; t < 64 * 64 / 4; t += 256) {
            int r  = t >> 4;
            int c4 = t & 15;
            int grow = row0 + r;
            float4 v = make_float4(0.f, 0.f, 0.f, 0.f);
            if (grow < n_nodes)
                v = *(const float4*)(feat + (size_t)grow * 128 + kk + c4 * 4);
            ((float4*)Fs)[t] = v;
        }
        __syncthreads();

        #pragma unroll 16
        for (int k = 0; k < 64; k++) {
            float4 w = *(const float4*)(Ws + k * 128 + tx * 4);
            #pragma unroll
            for (int r = 0; r < 8; r++) {
                float f = Fs[(ty * 8 + r) * 64 + k];
                acc[r][0] += f * w.x;
                acc[r][1] += f * w.y;
                acc[r][2] += f * w.z;
                acc[r][3] += f * w.w;
            }
        }
        __syncthreads();
    }

    #pragma unroll
    for (int r = 0; r < 8; r++) {
        int row = row0 + ty * 8 + r;
        if (row >= n_nodes) continue;
        int col = tx * 4;
        float4 v = make_float4(acc[r][0], acc[r][1], acc[r][2], acc[r][3]);
        *(float4*)(g_rep + (size_t)row * 128 + col) = v;
        float4 rv = make_float4(fmaxf(v.x, 0.f), fmaxf(v.y, 0.f),
                                fmaxf(v.z, 0.f), fmaxf(v.w, 0.f));
        *(float4*)(out + (size_t)row * 256 + col) = rv;
    }
}

// ---------------------------------------------------------------------------
// K5: gather per destination node, fused mean + relu.
// One warp per node; lane owns a float4 (4 columns) of the 128-wide row.
// ---------------------------------------------------------------------------
__global__ __launch_bounds__(256) void gather_kernel(float* __restrict__ out,
                                                     int n_nodes)
{
    int node = blockIdx.x * 8 + (threadIdx.x >> 5);
    int lane = threadIdx.x & 31;
    if (node >= n_nodes) return;

    int start = g_off[node];
    int end   = g_off[node + 1];

    float4 acc = make_float4(0.f, 0.f, 0.f, 0.f);
    for (int base = start; base < end; base += 32) {
        int n = min(32, end - base);
        int s = (lane < n) ? g_csr_src[base + lane] : 0;
        #pragma unroll 4
        for (int j = 0; j < n; j++) {
            int sj = __shfl_sync(0xffffffffu, s, j);
            float4 v = *(const float4*)(g_rep + (size_t)sj * 128 + lane * 4);
            acc.x += v.x; acc.y += v.y; acc.z += v.z; acc.w += v.w;
        }
    }

    float inv = 1.0f / fmaxf((float)(end - start), 1.0f);
    float4 r = make_float4(fmaxf(acc.x * inv, 0.f), fmaxf(acc.y * inv, 0.f),
                           fmaxf(acc.z * inv, 0.f), fmaxf(acc.w * inv, 0.f));
    *(float4*)(out + (size_t)node * 256 + 128 + lane * 4) = r;
}

// ---------------------------------------------------------------------------
extern "C" void kernel_launch(void* const* d_in, const int* in_sizes, int n_in,
                              void* d_out, int out_size) {
    const float* feat = (const float*)d_in[0];
    const float* W    = (const float*)d_in[1];
    const int*   esrc = (const int*)d_in[2];
    const int*   edst = (const int*)d_in[3];
    float* out = (float*)d_out;

    int n_nodes = in_sizes[0] / FEAT;
    int n_edges = in_sizes[2];

    zero_cnt_kernel<<<(n_nodes + 255) / 256, 256>>>(n_nodes);
    hist_kernel<<<(n_edges + 255) / 256, 256>>>(edst, n_edges);
    scan_kernel<<<1, 1024>>>(n_nodes);
    place_kernel<<<(n_edges + 255) / 256, 256>>>(esrc, edst, n_edges);
    gemm_kernel<<<(n_nodes + 63) / 64, 256>>>(feat, W, out, n_nodes);
    gather_kernel<<<(n_nodes + 7) / 8, 256>>>(out, n_nodes);
}

// round 3
// speedup vs baseline: 1.2891x; 1.0384x over previous
#include <cuda_runtime.h>
#include <cuda_fp16.h>

#define NMAX_NODES 50048
#define EMAX 1700000
#define FEAT 128

// Device scratch (no dynamic allocation allowed).
__device__ __half g_rep_h[NMAX_NODES * FEAT]; // nodes_rep = F @ W, fp16 copy
__device__ int    g_cnt[NMAX_NODES];          // in-degree counts
__device__ int    g_off[NMAX_NODES + 1];      // CSR row offsets
__device__ int    g_cur[NMAX_NODES];          // placement cursors
__device__ int    g_csr_src[EMAX];            // src ids grouped by dst

// ---------------------------------------------------------------------------
// K0: zero counts
// ---------------------------------------------------------------------------
__global__ void zero_cnt_kernel(int n_nodes) {
    int i = blockIdx.x * blockDim.x + threadIdx.x;
    if (i < n_nodes) g_cnt[i] = 0;
}

// ---------------------------------------------------------------------------
// K1: histogram of edge destinations — 4 edges per thread for atomic ILP
// ---------------------------------------------------------------------------
__global__ void hist_kernel(const int* __restrict__ dst, int n_edges) {
    int t = blockIdx.x * blockDim.x + threadIdx.x;
    int i0 = t * 4;
    if (i0 + 3 < n_edges) {
        int4 d = *(const int4*)(dst + i0);
        atomicAdd(&g_cnt[d.x], 1);
        atomicAdd(&g_cnt[d.y], 1);
        atomicAdd(&g_cnt[d.z], 1);
        atomicAdd(&g_cnt[d.w], 1);
    } else {
        for (int i = i0; i < n_edges; i++) atomicAdd(&g_cnt[dst[i]], 1);
    }
}

// ---------------------------------------------------------------------------
// K2: single-block exclusive scan of counts -> offsets (+ cursor copy)
// ---------------------------------------------------------------------------
__global__ __launch_bounds__(1024) void scan_kernel(int n_nodes) {
    __shared__ int warp_sums[32];
    const int tid  = threadIdx.x;
    const int lane = tid & 31, wid = tid >> 5;
    const int chunk = (n_nodes + 1023) / 1024;
    const int beg = tid * chunk;
    const int fin = min(beg + chunk, n_nodes);

    int sum = 0;
    for (int i = beg; i < fin; i++) sum += g_cnt[i];

    int v = sum;
    #pragma unroll
    for (int o = 1; o < 32; o <<= 1) {
        int t = __shfl_up_sync(0xffffffffu, v, o);
        if (lane >= o) v += t;
    }
    if (lane == 31) warp_sums[wid] = v;
    __syncthreads();
    if (wid == 0) {
        int w = warp_sums[lane];
        #pragma unroll
        for (int o = 1; o < 32; o <<= 1) {
            int t = __shfl_up_sync(0xffffffffu, w, o);
            if (lane >= o) w += t;
        }
        warp_sums[lane] = w;
    }
    __syncthreads();

    int excl = (v - sum) + (wid > 0 ? warp_sums[wid - 1] : 0);
    int run = excl;
    for (int i = beg; i < fin; i++) {
        g_off[i] = run;
        g_cur[i] = run;
        run += g_cnt[i];
    }
    if (tid == 1023) g_off[n_nodes] = run;
}

// ---------------------------------------------------------------------------
// K3: place edges into CSR order — 4 edges per thread for atomic ILP
// ---------------------------------------------------------------------------
__global__ void place_kernel(const int* __restrict__ src,
                             const int* __restrict__ dst, int n_edges) {
    int t = blockIdx.x * blockDim.x + threadIdx.x;
    int i0 = t * 4;
    if (i0 + 3 < n_edges) {
        int4 d = *(const int4*)(dst + i0);
        int4 s = *(const int4*)(src + i0);
        int p0 = atomicAdd(&g_cur[d.x], 1);
        int p1 = atomicAdd(&g_cur[d.y], 1);
        int p2 = atomicAdd(&g_cur[d.z], 1);
        int p3 = atomicAdd(&g_cur[d.w], 1);
        g_csr_src[p0] = s.x;
        g_csr_src[p1] = s.y;
        g_csr_src[p2] = s.z;
        g_csr_src[p3] = s.w;
    } else {
        for (int i = i0; i < n_edges; i++) {
            int pos = atomicAdd(&g_cur[dst[i]], 1);
            g_csr_src[pos] = src[i];
        }
    }
}

// ---------------------------------------------------------------------------
// K4: rep = F @ W (fp32); out[:, 0:128] = relu(rep); g_rep_h = half(rep)
// 256 threads, 64x128 tile, 8x4 microtile, 48KB smem.
// ---------------------------------------------------------------------------
__global__ __launch_bounds__(256) void gemm_kernel(
    const float* __restrict__ feat, const float* __restrict__ W,
    float* __restrict__ out, int n_nodes)
{
    __shared__ float Ws[64 * 128];
    __shared__ float Fs[64 * 64];

    const int tx = threadIdx.x & 31;
    const int ty = threadIdx.x >> 5;
    const int row0 = blockIdx.x * 64;

    float acc[8][4];
    #pragma unroll
    for (int r = 0; r < 8; r++)
        #pragma unroll
        for (int c = 0; c < 4; c++) acc[r][c] = 0.f;

    for (int kk = 0; kk < 128; kk += 64) {
        for (int t = threadIdx.x; t < 64 * 128 / 4; t += 256)
            ((float4*)Ws)[t] = ((const float4*)(W + kk * 128))[t];
        for (int t = threadIdx.x; t < 64 * 64 / 4; t += 256) {
            int r  = t >> 4;
            int c4 = t & 15;
            int grow = row0 + r;
            float4 v = make_float4(0.f, 0.f, 0.f, 0.f);
            if (grow < n_nodes)
                v = *(const float4*)(feat + (size_t)grow * 128 + kk + c4 * 4);
            ((float4*)Fs)[t] = v;
        }
        __syncthreads();

        #pragma unroll 16
        for (int k = 0; k < 64; k++) {
            float4 w = *(const float4*)(Ws + k * 128 + tx * 4);
            #pragma unroll
            for (int r = 0; r < 8; r++) {
                float f = Fs[(ty * 8 + r) * 64 + k];
                acc[r][0] += f * w.x;
                acc[r][1] += f * w.y;
                acc[r][2] += f * w.z;
                acc[r][3] += f * w.w;
            }
        }
        __syncthreads();
    }

    #pragma unroll
    for (int r = 0; r < 8; r++) {
        int row = row0 + ty * 8 + r;
        if (row >= n_nodes) continue;
        int col = tx * 4;
        // fp16 copy for the gather stage
        __half2 h0 = __floats2half2_rn(acc[r][0], acc[r][1]);
        __half2 h1 = __floats2half2_rn(acc[r][2], acc[r][3]);
        *(__half2*)(g_rep_h + (size_t)row * 128 + col)     = h0;
        *(__half2*)(g_rep_h + (size_t)row * 128 + col + 2) = h1;
        // fp32 relu self-representation
        float4 rv = make_float4(fmaxf(acc[r][0], 0.f), fmaxf(acc[r][1], 0.f),
                                fmaxf(acc[r][2], 0.f), fmaxf(acc[r][3], 0.f));
        *(float4*)(out + (size_t)row * 256 + col) = rv;
    }
}

// ---------------------------------------------------------------------------
// K5: gather per destination node (fp16 rows, fp32 accumulate), mean + relu.
// One warp per node; lane owns 4 columns (one uint2 = 4 halves per row).
// ---------------------------------------------------------------------------
__global__ __launch_bounds__(256) void gather_kernel(float* __restrict__ out,
                                                     int n_nodes)
{
    int node = blockIdx.x * 8 + (threadIdx.x >> 5);
    int lane = threadIdx.x & 31;
    if (node >= n_nodes) return;

    int start = g_off[node];
    int end   = g_off[node + 1];

    float4 acc = make_float4(0.f, 0.f, 0.f, 0.f);
    for (int base = start; base < end; base += 32) {
        int n = min(32, end - base);
        int s = (lane < n) ? g_csr_src[base + lane] : 0;
        #pragma unroll 4
        for (int j = 0; j < n; j++) {
            int sj = __shfl_sync(0xffffffffu, s, j);
            const __half2* p =
                (const __half2*)(g_rep_h + (size_t)sj * 128 + lane * 4);
            float2 f0 = __half22float2(p[0]);
            float2 f1 = __half22float2(p[1]);
            acc.x += f0.x; acc.y += f0.y; acc.z += f1.x; acc.w += f1.y;
        }
    }

    float inv = 1.0f / fmaxf((float)(end - start), 1.0f);
    float4 r = make_float4(fmaxf(acc.x * inv, 0.f), fmaxf(acc.y * inv, 0.f),
                           fmaxf(acc.z * inv, 0.f), fmaxf(acc.w * inv, 0.f));
    *(float4*)(out + (size_t)node * 256 + 128 + lane * 4) = r;
}

// ---------------------------------------------------------------------------
extern "C" void kernel_launch(void* const* d_in, const int* in_sizes, int n_in,
                              void* d_out, int out_size) {
    const float* feat = (const float*)d_in[0];
    const float* W    = (const float*)d_in[1];
    const int*   esrc = (const int*)d_in[2];
    const int*   edst = (const int*)d_in[3];
    float* out = (float*)d_out;

    int n_nodes = in_sizes[0] / FEAT;
    int n_edges = in_sizes[2];

    zero_cnt_kernel<<<(n_nodes + 255) / 256, 256>>>(n_nodes);
    {
        int threads4 = (n_edges + 3) / 4;
        hist_kernel<<<(threads4 + 255) / 256, 256>>>(edst, n_edges);
    }
    scan_kernel<<<1, 1024>>>(n_nodes);
    {
        int threads4 = (n_edges + 3) / 4;
        place_kernel<<<(threads4 + 255) / 256, 256>>>(esrc, edst, n_edges);
    }
    gemm_kernel<<<(n_nodes + 63) / 64, 256>>>(feat, W, out, n_nodes);
    gather_kernel<<<(n_nodes + 7) / 8, 256>>>(out, n_nodes);
}

// round 4
// speedup vs baseline: 1.3447x; 1.0432x over previous
#include <cuda_runtime.h>
#include <cuda_fp16.h>

#define NMAX_NODES 50048
#define EMAX 1700000
#define FEAT 128

// Device scratch (no dynamic allocation allowed).
__device__ __half g_rep_h[NMAX_NODES * FEAT]; // nodes_rep = F @ W, fp16 copy
__device__ int    g_cnt[NMAX_NODES];          // in-degree counts
__device__ int    g_off[NMAX_NODES + 1];      // CSR row offsets
__device__ int    g_cur[NMAX_NODES];          // placement cursors
__device__ int    g_csr_src[EMAX];            // src ids grouped by dst

__device__ __forceinline__ unsigned long long pack2(float a, float b) {
    unsigned long long r;
    asm("mov.b64 %0, {%1, %2};" : "=l"(r)
        : "r"(__float_as_uint(a)), "r"(__float_as_uint(b)));
    return r;
}
__device__ __forceinline__ void unpack2(unsigned long long v, float& a, float& b) {
    unsigned int lo, hi;
    asm("mov.b64 {%0, %1}, %2;" : "=r"(lo), "=r"(hi) : "l"(v));
    a = __uint_as_float(lo); b = __uint_as_float(hi);
}
__device__ __forceinline__ void ffma2(unsigned long long& acc,
                                      unsigned long long a,
                                      unsigned long long b) {
    asm("fma.rn.f32x2 %0, %1, %2, %0;" : "+l"(acc) : "l"(a), "l"(b));
}

// ---------------------------------------------------------------------------
// K0: zero counts
// ---------------------------------------------------------------------------
__global__ void zero_cnt_kernel(int n_nodes) {
    int i = blockIdx.x * blockDim.x + threadIdx.x;
    if (i < n_nodes) g_cnt[i] = 0;
}

// ---------------------------------------------------------------------------
// GEMM block body: 64 rows x 128 cols, FFMA2 (fp32x2) inner loop.
// out[:, 0:128] = relu(rep); g_rep_h = half(rep)
// ---------------------------------------------------------------------------
__device__ void gemm_block(const float* __restrict__ feat,
                           const float* __restrict__ W,
                           float* __restrict__ out,
                           int n_nodes, int row0)
{
    __shared__ float Ws[64 * 128];
    __shared__ float Fs[64 * 64];

    const int tx = threadIdx.x & 31;
    const int ty = threadIdx.x >> 5;

    unsigned long long acc01[8], acc23[8];
    #pragma unroll
    for (int r = 0; r < 8; r++) { acc01[r] = 0ULL; acc23[r] = 0ULL; }

    for (int kk = 0; kk < 128; kk += 64) {
        for (int t = threadIdx.x; t < 64 * 128 / 4; t += 256)
            ((float4*)Ws)[t] = ((const float4*)(W + kk * 128))[t];
        for (int t = threadIdx.x; t < 64 * 64 / 4; t += 256) {
            int r  = t >> 4;
            int c4 = t & 15;
            int grow = row0 + r;
            float4 v = make_float4(0.f, 0.f, 0.f, 0.f);
            if (grow < n_nodes)
                v = *(const float4*)(feat + (size_t)grow * 128 + kk + c4 * 4);
            ((float4*)Fs)[t] = v;
        }
        __syncthreads();

        #pragma unroll 8
        for (int k = 0; k < 64; k++) {
            const unsigned long long* wp =
                (const unsigned long long*)(Ws + k * 128 + tx * 4);
            unsigned long long w01 = wp[0];
            unsigned long long w23 = wp[1];
            #pragma unroll
            for (int r = 0; r < 8; r++) {
                float f = Fs[(ty * 8 + r) * 64 + k];
                unsigned long long ff = pack2(f, f);
                ffma2(acc01[r], ff, w01);
                ffma2(acc23[r], ff, w23);
            }
        }
        __syncthreads();
    }

    #pragma unroll
    for (int r = 0; r < 8; r++) {
        int row = row0 + ty * 8 + r;
        if (row >= n_nodes) continue;
        int col = tx * 4;
        float a0, a1, a2, a3;
        unpack2(acc01[r], a0, a1);
        unpack2(acc23[r], a2, a3);
        __half2 h0 = __floats2half2_rn(a0, a1);
        __half2 h1 = __floats2half2_rn(a2, a3);
        *(__half2*)(g_rep_h + (size_t)row * 128 + col)     = h0;
        *(__half2*)(g_rep_h + (size_t)row * 128 + col + 2) = h1;
        float4 rv = make_float4(fmaxf(a0, 0.f), fmaxf(a1, 0.f),
                                fmaxf(a2, 0.f), fmaxf(a3, 0.f));
        *(float4*)(out + (size_t)row * 256 + col) = rv;
    }
}

// ---------------------------------------------------------------------------
// K1: gemm (first half of rows) in low blocks || dst-histogram in high blocks
// ---------------------------------------------------------------------------
__global__ __launch_bounds__(256) void gemm_hist_kernel(
    const float* __restrict__ feat, const float* __restrict__ W,
    float* __restrict__ out, int n_nodes, int n_gemm_blocks,
    const int* __restrict__ dst, int n_edges)
{
    if (blockIdx.x < n_gemm_blocks) {
        gemm_block(feat, W, out, n_nodes, blockIdx.x * 64);
    } else {
        int t = (blockIdx.x - n_gemm_blocks) * blockDim.x + threadIdx.x;
        int i0 = t * 4;
        if (i0 + 3 < n_edges) {
            int4 d = *(const int4*)(dst + i0);
            atomicAdd(&g_cnt[d.x], 1);
            atomicAdd(&g_cnt[d.y], 1);
            atomicAdd(&g_cnt[d.z], 1);
            atomicAdd(&g_cnt[d.w], 1);
        } else {
            for (int i = i0; i < n_edges; i++) atomicAdd(&g_cnt[dst[i]], 1);
        }
    }
}

// ---------------------------------------------------------------------------
// K2: single-block exclusive scan of counts -> offsets (+ cursor copy)
// ---------------------------------------------------------------------------
__global__ __launch_bounds__(1024) void scan_kernel(int n_nodes) {
    __shared__ int warp_sums[32];
    const int tid  = threadIdx.x;
    const int lane = tid & 31, wid = tid >> 5;
    const int chunk = (n_nodes + 1023) / 1024;
    const int beg = tid * chunk;
    const int fin = min(beg + chunk, n_nodes);

    int sum = 0;
    for (int i = beg; i < fin; i++) sum += g_cnt[i];

    int v = sum;
    #pragma unroll
    for (int o = 1; o < 32; o <<= 1) {
        int t = __shfl_up_sync(0xffffffffu, v, o);
        if (lane >= o) v += t;
    }
    if (lane == 31) warp_sums[wid] = v;
    __syncthreads();
    if (wid == 0) {
        int w = warp_sums[lane];
        #pragma unroll
        for (int o = 1; o < 32; o <<= 1) {
            int t = __shfl_up_sync(0xffffffffu, w, o);
            if (lane >= o) w += t;
        }
        warp_sums[lane] = w;
    }
    __syncthreads();

    int excl = (v - sum) + (wid > 0 ? warp_sums[wid - 1] : 0);
    int run = excl;
    for (int i = beg; i < fin; i++) {
        g_off[i] = run;
        g_cur[i] = run;
        run += g_cnt[i];
    }
    if (tid == 1023) g_off[n_nodes] = run;
}

// ---------------------------------------------------------------------------
// K3: gemm (second half of rows) in low blocks || CSR placement in high blocks
// ---------------------------------------------------------------------------
__global__ __launch_bounds__(256) void gemm_place_kernel(
    const float* __restrict__ feat, const float* __restrict__ W,
    float* __restrict__ out, int n_nodes, int n_gemm_blocks, int row_base,
    const int* __restrict__ src, const int* __restrict__ dst, int n_edges)
{
    if (blockIdx.x < n_gemm_blocks) {
        gemm_block(feat, W, out, n_nodes, row_base + blockIdx.x * 64);
    } else {
        int t = (blockIdx.x - n_gemm_blocks) * blockDim.x + threadIdx.x;
        int i0 = t * 4;
        if (i0 + 3 < n_edges) {
            int4 d = *(const int4*)(dst + i0);
            int4 s = *(const int4*)(src + i0);
            int p0 = atomicAdd(&g_cur[d.x], 1);
            int p1 = atomicAdd(&g_cur[d.y], 1);
            int p2 = atomicAdd(&g_cur[d.z], 1);
            int p3 = atomicAdd(&g_cur[d.w], 1);
            g_csr_src[p0] = s.x;
            g_csr_src[p1] = s.y;
            g_csr_src[p2] = s.z;
            g_csr_src[p3] = s.w;
        } else {
            for (int i = i0; i < n_edges; i++) {
                int pos = atomicAdd(&g_cur[dst[i]], 1);
                g_csr_src[pos] = src[i];
            }
        }
    }
}

// ---------------------------------------------------------------------------
// K4: gather per destination node, fused mean + relu.
// One warp per node. Half-warps process 2 edges per step: lane = 16*half +
// col8; each lane loads 16B (8 halves) of the fp16 row -> 1 LDG.128 covers
// 2 edges per warp-instruction. Final shfl-16 reduction combines halves.
// ---------------------------------------------------------------------------
__global__ __launch_bounds__(256) void gather_kernel(float* __restrict__ out,
                                                     int n_nodes)
{
    int node = blockIdx.x * 8 + (threadIdx.x >> 5);
    int lane = threadIdx.x & 31;
    if (node >= n_nodes) return;

    const int half = lane >> 4;     // which edge of the pair
    const int col8 = lane & 15;     // owns 8 cols: [col8*8, col8*8+8)

    int start = g_off[node];
    int end   = g_off[node + 1];
    int deg   = end - start;

    float acc[8];
    #pragma unroll
    for (int i = 0; i < 8; i++) acc[i] = 0.f;

    for (int base = start; base < end; base += 32) {
        int n = min(32, end - base);
        int s = (lane < n) ? g_csr_src[base + lane] : 0;
        #pragma unroll 4
        for (int j0 = 0; j0 < 32; j0 += 2) {
            if (j0 >= n) break;
            int j = j0 + half;
            int sj = __shfl_sync(0xffffffffu, s, j < n ? j : 0);
            if (j < n) {
                uint4 v = *(const uint4*)(g_rep_h + (size_t)sj * 128 + col8 * 8);
                float2 f0 = __half22float2(*(__half2*)&v.x);
                float2 f1 = __half22float2(*(__half2*)&v.y);
                float2 f2 = __half22float2(*(__half2*)&v.z);
                float2 f3 = __half22float2(*(__half2*)&v.w);
                acc[0] += f0.x; acc[1] += f0.y;
                acc[2] += f1.x; acc[3] += f1.y;
                acc[4] += f2.x; acc[5] += f2.y;
                acc[6] += f3.x; acc[7] += f3.y;
            }
        }
    }

    // combine the two half-warp partial sums
    #pragma unroll
    for (int i = 0; i < 8; i++)
        acc[i] += __shfl_down_sync(0xffffffffu, acc[i], 16);

    if (half == 0) {
        float inv = 1.0f / fmaxf((float)deg, 1.0f);
        float4 r0 = make_float4(fmaxf(acc[0] * inv, 0.f), fmaxf(acc[1] * inv, 0.f),
                                fmaxf(acc[2] * inv, 0.f), fmaxf(acc[3] * inv, 0.f));
        float4 r1 = make_float4(fmaxf(acc[4] * inv, 0.f), fmaxf(acc[5] * inv, 0.f),
                                fmaxf(acc[6] * inv, 0.f), fmaxf(acc[7] * inv, 0.f));
        float* o = out + (size_t)node * 256 + 128 + col8 * 8;
        *(float4*)(o)     = r0;
        *(float4*)(o + 4) = r1;
    }
}

// ---------------------------------------------------------------------------
extern "C" void kernel_launch(void* const* d_in, const int* in_sizes, int n_in,
                              void* d_out, int out_size) {
    const float* feat = (const float*)d_in[0];
    const float* W    = (const float*)d_in[1];
    const int*   esrc = (const int*)d_in[2];
    const int*   edst = (const int*)d_in[3];
    float* out = (float*)d_out;

    int n_nodes = in_sizes[0] / FEAT;
    int n_edges = in_sizes[2];

    int half_rows = ((n_nodes / 2) + 63) & ~63;      // multiple of 64
    int g1 = half_rows / 64;                         // gemm blocks, first half
    int g2 = (n_nodes - half_rows + 63) / 64;        // gemm blocks, second half
    int edge_blocks = ((n_edges + 3) / 4 + 255) / 256;

    zero_cnt_kernel<<<(n_nodes + 255) / 256, 256>>>(n_nodes);
    gemm_hist_kernel<<<g1 + edge_blocks, 256>>>(feat, W, out, n_nodes, g1,
                                                edst, n_edges);
    scan_kernel<<<1, 1024>>>(n_nodes);
    gemm_place_kernel<<<g2 + edge_blocks, 256>>>(feat, W, out, n_nodes, g2,
                                                 half_rows, esrc, edst, n_edges);
    gather_kernel<<<(n_nodes + 7) / 8, 256>>>(out, n_nodes);
}

// round 5
// speedup vs baseline: 1.4514x; 1.0793x over previous
#include <cuda_runtime.h>
#include <cuda_fp16.h>

#define NMAX_NODES 50048
#define EMAX 1700000
#define FEAT 128

// Device scratch (no dynamic allocation allowed).
__device__ __half g_rep_h[NMAX_NODES * FEAT]; // nodes_rep = F @ W, fp16 copy
__device__ int    g_cnt[NMAX_NODES];          // in-degree counts
__device__ int    g_off[NMAX_NODES + 1];      // CSR row offsets
__device__ int    g_cur[NMAX_NODES];          // placement cursors
__device__ int    g_csr_src[EMAX];            // src ids grouped by dst

__device__ __forceinline__ unsigned int f2tf32(float x) {
    unsigned int u;
    asm("cvt.rna.tf32.f32 %0, %1;" : "=r"(u) : "f"(x));
    return u;
}

// ---------------------------------------------------------------------------
// K0: zero counts
// ---------------------------------------------------------------------------
__global__ void zero_cnt_kernel(int n_nodes) {
    int i = blockIdx.x * blockDim.x + threadIdx.x;
    if (i < n_nodes) g_cnt[i] = 0;
}

// ---------------------------------------------------------------------------
// K1: histogram of edge destinations (4 edges/thread)
// ---------------------------------------------------------------------------
__global__ void hist_kernel(const int* __restrict__ dst, int n_edges) {
    int t = blockIdx.x * blockDim.x + threadIdx.x;
    int i0 = t * 4;
    if (i0 + 3 < n_edges) {
        int4 d = *(const int4*)(dst + i0);
        atomicAdd(&g_cnt[d.x], 1);
        atomicAdd(&g_cnt[d.y], 1);
        atomicAdd(&g_cnt[d.z], 1);
        atomicAdd(&g_cnt[d.w], 1);
    } else {
        for (int i = i0; i < n_edges; i++) atomicAdd(&g_cnt[dst[i]], 1);
    }
}

// ---------------------------------------------------------------------------
// K2: single-block exclusive scan of counts -> offsets (+ cursor copy)
// ---------------------------------------------------------------------------
__global__ __launch_bounds__(1024) void scan_kernel(int n_nodes) {
    __shared__ int warp_sums[32];
    const int tid  = threadIdx.x;
    const int lane = tid & 31, wid = tid >> 5;
    const int chunk = (n_nodes + 1023) / 1024;
    const int beg = tid * chunk;
    const int fin = min(beg + chunk, n_nodes);

    int sum = 0;
    for (int i = beg; i < fin; i++) sum += g_cnt[i];

    int v = sum;
    #pragma unroll
    for (int o = 1; o < 32; o <<= 1) {
        int t = __shfl_up_sync(0xffffffffu, v, o);
        if (lane >= o) v += t;
    }
    if (lane == 31) warp_sums[wid] = v;
    __syncthreads();
    if (wid == 0) {
        int w = warp_sums[lane];
        #pragma unroll
        for (int o = 1; o < 32; o <<= 1) {
            int t = __shfl_up_sync(0xffffffffu, w, o);
            if (lane >= o) w += t;
        }
        warp_sums[lane] = w;
    }
    __syncthreads();

    int excl = (v - sum) + (wid > 0 ? warp_sums[wid - 1] : 0);
    int run = excl;
    for (int i = beg; i < fin; i++) {
        g_off[i] = run;
        g_cur[i] = run;
        run += g_cnt[i];
    }
    if (tid == 1023) g_off[n_nodes] = run;
}

// ---------------------------------------------------------------------------
// K3: tf32 tensor-core GEMM (low blocks)  ||  CSR placement (high blocks)
// GEMM: 128x128 CTA tile, 8 warps (4 M x 2 N), warp tile 32x64,
//       mma.sync.m16n8k8 tf32, K chunked by 32, fp32 accumulate.
// Epilogue: out[:,0:128] = relu(rep) fp32 ; g_rep_h = half(rep).
// ---------------------------------------------------------------------------
__global__ __launch_bounds__(256) void gemm_place_kernel(
    const float* __restrict__ feat, const float* __restrict__ W,
    float* __restrict__ out, int n_nodes, int n_gemm_blocks,
    const int* __restrict__ src, const int* __restrict__ dst, int n_edges)
{
    __shared__ unsigned int As[128][36];   // tf32 bits, [m][k-within-chunk]
    __shared__ unsigned int Bs[32][136];   // tf32 bits, [k-within-chunk][n]

    if (blockIdx.x >= n_gemm_blocks) {
        // ---------------- CSR placement ----------------
        int t = (blockIdx.x - n_gemm_blocks) * blockDim.x + threadIdx.x;
        int i0 = t * 4;
        if (i0 + 3 < n_edges) {
            int4 d = *(const int4*)(dst + i0);
            int4 s = *(const int4*)(src + i0);
            int p0 = atomicAdd(&g_cur[d.x], 1);
            int p1 = atomicAdd(&g_cur[d.y], 1);
            int p2 = atomicAdd(&g_cur[d.z], 1);
            int p3 = atomicAdd(&g_cur[d.w], 1);
            g_csr_src[p0] = s.x;
            g_csr_src[p1] = s.y;
            g_csr_src[p2] = s.z;
            g_csr_src[p3] = s.w;
        } else {
            for (int i = i0; i < n_edges; i++) {
                int pos = atomicAdd(&g_cur[dst[i]], 1);
                g_csr_src[pos] = src[i];
            }
        }
        return;
    }

    // ---------------- tf32 GEMM ----------------
    const int tid    = threadIdx.x;
    const int wid    = tid >> 5;
    const int lane   = tid & 31;
    const int gr     = lane >> 2;       // group row   (0..7)
    const int gc     = lane & 3;        // thread-in-group (0..3)
    const int warp_m = wid & 3;         // 4 warps over M (32 rows each)
    const int warp_n = wid >> 2;        // 2 warps over N (64 cols each)
    const int row0   = blockIdx.x * 128;

    float acc[2][8][4];
    #pragma unroll
    for (int mt = 0; mt < 2; mt++)
        #pragma unroll
        for (int nt = 0; nt < 8; nt++)
            #pragma unroll
            for (int i = 0; i < 4; i++) acc[mt][nt][i] = 0.f;

    for (int kk = 0; kk < 128; kk += 32) {
        // stage A: 128 rows x 32 k (1024 float4, 4 per thread)
        #pragma unroll
        for (int it = 0; it < 4; it++) {
            int i  = tid + it * 256;      // 0..1023
            int r  = i >> 3;              // row in tile
            int c4 = i & 7;               // float4 index in 32-k slice
            float4 v = make_float4(0.f, 0.f, 0.f, 0.f);
            int grow = row0 + r;
            if (grow < n_nodes)
                v = *(const float4*)(feat + (size_t)grow * 128 + kk + c4 * 4);
            As[r][c4 * 4 + 0] = f2tf32(v.x);
            As[r][c4 * 4 + 1] = f2tf32(v.y);
            As[r][c4 * 4 + 2] = f2tf32(v.z);
            As[r][c4 * 4 + 3] = f2tf32(v.w);
        }
        // stage B: 32 k-rows x 128 n (1024 float4, 4 per thread)
        #pragma unroll
        for (int it = 0; it < 4; it++) {
            int i  = tid + it * 256;
            int r  = i >> 5;              // k row (0..31)
            int c4 = i & 31;              // float4 index along n
            float4 v = *(const float4*)(W + (size_t)(kk + r) * 128 + c4 * 4);
            Bs[r][c4 * 4 + 0] = f2tf32(v.x);
            Bs[r][c4 * 4 + 1] = f2tf32(v.y);
            Bs[r][c4 * 4 + 2] = f2tf32(v.z);
            Bs[r][c4 * 4 + 3] = f2tf32(v.w);
        }
        __syncthreads();

        #pragma unroll
        for (int k8 = 0; k8 < 32; k8 += 8) {
            unsigned int a[2][4], b[8][2];
            #pragma unroll
            for (int mt = 0; mt < 2; mt++) {
                int mb = warp_m * 32 + mt * 16;
                a[mt][0] = As[mb + gr    ][k8 + gc    ];
                a[mt][1] = As[mb + gr + 8][k8 + gc    ];
                a[mt][2] = As[mb + gr    ][k8 + gc + 4];
                a[mt][3] = As[mb + gr + 8][k8 + gc + 4];
            }
            #pragma unroll
            for (int nt = 0; nt < 8; nt++) {
                int nb = warp_n * 64 + nt * 8;
                b[nt][0] = Bs[k8 + gc    ][nb + gr];
                b[nt][1] = Bs[k8 + gc + 4][nb + gr];
            }
            #pragma unroll
            for (int mt = 0; mt < 2; mt++)
                #pragma unroll
                for (int nt = 0; nt < 8; nt++) {
                    asm("mma.sync.aligned.m16n8k8.row.col.f32.tf32.tf32.f32 "
                        "{%0,%1,%2,%3}, {%4,%5,%6,%7}, {%8,%9}, {%0,%1,%2,%3};"
                        : "+f"(acc[mt][nt][0]), "+f"(acc[mt][nt][1]),
                          "+f"(acc[mt][nt][2]), "+f"(acc[mt][nt][3])
                        : "r"(a[mt][0]), "r"(a[mt][1]),
                          "r"(a[mt][2]), "r"(a[mt][3]),
                          "r"(b[nt][0]), "r"(b[nt][1]));
                }
        }
        __syncthreads();
    }

    // epilogue: c0,c1 -> (row_lo, col..col+1); c2,c3 -> (row_lo+8, ...)
    #pragma unroll
    for (int mt = 0; mt < 2; mt++) {
        int row_lo = row0 + warp_m * 32 + mt * 16 + gr;
        int row_hi = row_lo + 8;
        #pragma unroll
        for (int nt = 0; nt < 8; nt++) {
            int col = warp_n * 64 + nt * 8 + gc * 2;
            float c0 = acc[mt][nt][0], c1 = acc[mt][nt][1];
            float c2 = acc[mt][nt][2], c3 = acc[mt][nt][3];
            if (row_lo < n_nodes) {
                *(__half2*)(g_rep_h + (size_t)row_lo * 128 + col) =
                    __floats2half2_rn(c0, c1);
                *(float2*)(out + (size_t)row_lo * 256 + col) =
                    make_float2(fmaxf(c0, 0.f), fmaxf(c1, 0.f));
            }
            if (row_hi < n_nodes) {
                *(__half2*)(g_rep_h + (size_t)row_hi * 128 + col) =
                    __floats2half2_rn(c2, c3);
                *(float2*)(out + (size_t)row_hi * 256 + col) =
                    make_float2(fmaxf(c2, 0.f), fmaxf(c3, 0.f));
            }
        }
    }
}

// ---------------------------------------------------------------------------
// K4: gather per destination node, fused mean + relu.
// One warp per node; half-warps process 2 edges per step (lane = 16*half+col8,
// 16B of fp16 row per lane), shfl-16 reduction at the end.
// ---------------------------------------------------------------------------
__global__ __launch_bounds__(256) void gather_kernel(float* __restrict__ out,
                                                     int n_nodes)
{
    int node = blockIdx.x * 8 + (threadIdx.x >> 5);
    int lane = threadIdx.x & 31;
    if (node >= n_nodes) return;

    const int half = lane >> 4;
    const int col8 = lane & 15;

    int start = g_off[node];
    int end   = g_off[node + 1];
    int deg   = end - start;

    float acc[8];
    #pragma unroll
    for (int i = 0; i < 8; i++) acc[i] = 0.f;

    for (int base = start; base < end; base += 32) {
        int n = min(32, end - base);
        int s = (lane < n) ? g_csr_src[base + lane] : 0;
        #pragma unroll 4
        for (int j0 = 0; j0 < 32; j0 += 2) {
            if (j0 >= n) break;
            int j = j0 + half;
            int sj = __shfl_sync(0xffffffffu, s, j < n ? j : 0);
            if (j < n) {
                uint4 v = *(const uint4*)(g_rep_h + (size_t)sj * 128 + col8 * 8);
                float2 f0 = __half22float2(*(__half2*)&v.x);
                float2 f1 = __half22float2(*(__half2*)&v.y);
                float2 f2 = __half22float2(*(__half2*)&v.z);
                float2 f3 = __half22float2(*(__half2*)&v.w);
                acc[0] += f0.x; acc[1] += f0.y;
                acc[2] += f1.x; acc[3] += f1.y;
                acc[4] += f2.x; acc[5] += f2.y;
                acc[6] += f3.x; acc[7] += f3.y;
            }
        }
    }

    #pragma unroll
    for (int i = 0; i < 8; i++)
        acc[i] += __shfl_down_sync(0xffffffffu, acc[i], 16);

    if (half == 0) {
        float inv = 1.0f / fmaxf((float)deg, 1.0f);
        float4 r0 = make_float4(fmaxf(acc[0] * inv, 0.f), fmaxf(acc[1] * inv, 0.f),
                                fmaxf(acc[2] * inv, 0.f), fmaxf(acc[3] * inv, 0.f));
        float4 r1 = make_float4(fmaxf(acc[4] * inv, 0.f), fmaxf(acc[5] * inv, 0.f),
                                fmaxf(acc[6] * inv, 0.f), fmaxf(acc[7] * inv, 0.f));
        float* o = out + (size_t)node * 256 + 128 + col8 * 8;
        *(float4*)(o)     = r0;
        *(float4*)(o + 4) = r1;
    }
}

// ---------------------------------------------------------------------------
extern "C" void kernel_launch(void* const* d_in, const int* in_sizes, int n_in,
                              void* d_out, int out_size) {
    const float* feat = (const float*)d_in[0];
    const float* W    = (const float*)d_in[1];
    const int*   esrc = (const int*)d_in[2];
    const int*   edst = (const int*)d_in[3];
    float* out = (float*)d_out;

    int n_nodes = in_sizes[0] / FEAT;
    int n_edges = in_sizes[2];

    int gemm_blocks = (n_nodes + 127) / 128;
    int edge_blocks = ((n_edges + 3) / 4 + 255) / 256;

    zero_cnt_kernel<<<(n_nodes + 255) / 256, 256>>>(n_nodes);
    hist_kernel<<<edge_blocks, 256>>>(edst, n_edges);
    scan_kernel<<<1, 1024>>>(n_nodes);
    gemm_place_kernel<<<gemm_blocks + edge_blocks, 256>>>(
        feat, W, out, n_nodes, gemm_blocks, esrc, edst, n_edges);
    gather_kernel<<<(n_nodes + 7) / 8, 256>>>(out, n_nodes);
}